// round 14
// baseline (speedup 1.0000x reference)
#include <cuda_runtime.h>

// SmoothRankAP (quick_forward, sigmoid, tau=0.01), B=512. Single fused kernel.
// sigma(x) = 0.5*tanh(x/2)+0.5, x/2 = 50*(s_j - s_i).
//   T_all(i) = sum_j tanh(50 s_j - 50 s_i)        -> sim_all = 0.5*T_all + 256.5
//   T_pos(i) = sum_j tanh(...) * t_j              -> sim_pos = 0.5*(T_pos - tanh(50 s_q - 50 s_i) + npos) + 0.5
//   ap[q] = (1/npos) * sum_{i: t=1} sim_pos/sim_all;  out = 1 - mean_q ap
//
// 512 blocks x 256 threads, zero smem, zero barriers, per-warp packed
// fixed-point atomic finish. Warp reductions via redux.sync.add.s32 (sm_80+)
// on 2^20 fixed-point lane partials: 1 HW instruction per sum instead of a
// 5-level SHFL chain; integer add -> exact & deterministic.

static constexpr int BB = 512;
static constexpr unsigned long long NWARPS_TOTAL = 512ull * 8ull;   // 4096

// [63:13] fixed-point ap-sum (scale 2^32), [12:0] arrival count (max 4096).
__device__ unsigned long long g_accum = 0ull;

__device__ __forceinline__ float tanh_approx(float x) {
    float y;
    asm("tanh.approx.f32 %0, %1;" : "=f"(y) : "f"(x));
    return y;
}

// Warp-wide integer sum, single instruction (sm_80+). Uniform result.
__device__ __forceinline__ int redux_add_s32(int x) {
    int y;
    asm("redux.sync.add.s32 %0, %1, 0xffffffff;" : "=r"(y) : "r"(x));
    return y;
}

// float warp-sum via 2^20 fixed point (values bounded by ~512 -> fits s32)
__device__ __forceinline__ float redux_fix20(float x) {
    const int i = __float2int_rn(x * 1048576.0f);
    return (float)redux_add_s32(i) * (1.0f / 1048576.0f);
}

__global__ __launch_bounds__(256) void smoothap_fused_kernel(
    const float* __restrict__ scores,
    const float* __restrict__ target,
    float* __restrict__ out)
{
    const int tid  = threadIdx.x;
    const int wid  = tid >> 5;        // 0..7
    const int lane = tid & 31;
    const int q    = blockIdx.x;

    const float* __restrict__ srow = scores + (size_t)q * BB;
    const float* __restrict__ trow = target + (size_t)q * BB;

    // own chunk (warp w owns cols [64w,64w+64); lane l -> cols 64w+2l,+1).
    // Pre-negated & scaled so broadcasts give -50*s_i directly.
    const float2 so = __ldg(reinterpret_cast<const float2*>(srow + 64 * wid) + lane);
    const float2 to = __ldg(reinterpret_cast<const float2*>(trow + 64 * wid) + lane);
    const float nhx = so.x * -50.0f, nhy = so.y * -50.0f;

    // full-row register cache (UNSCALED): 4 x LDG.128 each
    const float4* __restrict__ srow4 = reinterpret_cast<const float4*>(srow);
    const float4* __restrict__ trow4 = reinterpret_cast<const float4*>(trow);
    float4 sv[4], tv[4];
    #pragma unroll
    for (int k = 0; k < 4; ++k) {
        sv[k] = __ldg(srow4 + k * 32 + lane);
        tv[k] = __ldg(trow4 + k * 32 + lane);
    }
    const float sq = __ldg(srow + q);             // broadcast load, unscaled

    // positive mask over own chunk
    unsigned m0 = __ballot_sync(0xffffffffu, to.x > 0.5f);
    unsigned m1 = __ballot_sync(0xffffffffu, to.y > 0.5f);
    unsigned long long mm = ((unsigned long long)m1 << 32) | (unsigned long long)m0;

    float acc = 0.0f;                 // uniform across lanes (redux results uniform)
    float fnp = 1.0f;

    if (mm) {
        // npos: exact integer lane partial + one s32 redux
        const float ts = ((tv[0].x + tv[0].y) + (tv[0].z + tv[0].w))
                       + ((tv[1].x + tv[1].y) + (tv[1].z + tv[1].w))
                       + ((tv[2].x + tv[2].y) + (tv[2].z + tv[2].w))
                       + ((tv[3].x + tv[3].y) + (tv[3].z + tv[3].w));
        fnp = (float)redux_add_s32(__float2int_rn(ts));   // exact, >= 1

        do {
            const int b0 = __ffsll(mm) - 1;  mm &= mm - 1;
            const bool two = (mm != 0ull);
            int b1 = b0;
            if (two) { b1 = __ffsll(mm) - 1; mm &= mm - 1; }

            // broadcast -50*s_i from pre-negated own-chunk registers
            const float x0 = __shfl_sync(0xffffffffu, nhx, b0 & 31);
            const float y0 = __shfl_sync(0xffffffffu, nhy, b0 & 31);
            const float nhiA = (b0 < 32) ? x0 : y0;
            const float x1 = __shfl_sync(0xffffffffu, nhx, b1 & 31);
            const float y1 = __shfl_sync(0xffffffffu, nhy, b1 & 31);
            const float nhiB = (b1 < 32) ? x1 : y1;

            float aA = 0.0f, pA = 0.0f, aB = 0.0f, pB = 0.0f;
            #pragma unroll
            for (int k = 0; k < 4; ++k) {
                #define SRA_STEP(S, T)                                        \
                    { const float thA = tanh_approx(fmaf((S), 50.0f, nhiA));  \
                      const float thB = tanh_approx(fmaf((S), 50.0f, nhiB));  \
                      aA += thA; pA = fmaf(thA, (T), pA);                     \
                      aB += thB; pB = fmaf(thB, (T), pB); }
                SRA_STEP(sv[k].x, tv[k].x)
                SRA_STEP(sv[k].y, tv[k].y)
                SRA_STEP(sv[k].z, tv[k].z)
                SRA_STEP(sv[k].w, tv[k].w)
                #undef SRA_STEP
            }

            // single-instruction warp sums (fixed-point s32, uniform result)
            aA = redux_fix20(aA);
            pA = redux_fix20(pA);
            const float thqA = tanh_approx(fmaf(sq, 50.0f, nhiA));
            acc += __fdividef(0.5f * (pA - thqA + fnp) + 0.5f, 0.5f * aA + 256.5f);
            if (two) {
                aB = redux_fix20(aB);
                pB = redux_fix20(pB);
                const float thqB = tanh_approx(fmaf(sq, 50.0f, nhiB));
                acc += __fdividef(0.5f * (pB - thqB + fnp) + 0.5f, 0.5f * aB + 256.5f);
            }
        } while (mm);
    }

    // ---- per-warp autonomous finish: one packed atomic, no barrier ----
    if (lane == 0) {
        const float w_ap = __fdividef(acc, fnp);   // this warp's share of ap[q]
        unsigned long long contrib =
            ((unsigned long long)__float2ull_rn(w_ap * 4294967296.0f) << 13) | 1ull;
        unsigned long long nv = atomicAdd(&g_accum, contrib) + contrib;

        if ((nv & 0x1FFFull) == NWARPS_TOTAL) {    // unique last-arriving warp
            const double sum_ap = (double)(nv >> 13) * (1.0 / 4294967296.0);
            out[0] = (float)(1.0 - sum_ap * (1.0 / (double)BB));
            atomicExch(&g_accum, 0ull);            // reset for next graph replay
        }
    }
}

extern "C" void kernel_launch(void* const* d_in, const int* in_sizes, int n_in,
                              void* d_out, int out_size)
{
    const float* scores = (const float*)d_in[0];
    const float* target = (const float*)d_in[1];
    smoothap_fused_kernel<<<BB, 256>>>(scores, target, (float*)d_out);
}

// round 15
// speedup vs baseline: 1.0295x; 1.0295x over previous
#include <cuda_runtime.h>

// SmoothRankAP (quick_forward, sigmoid, tau=0.01), B=512. Single fused kernel.
// sigma(x) = 0.5*tanh(x/2)+0.5, x/2 = 50*(s_j - s_i).
//   T_all(i) = sum_j tanh(50 s_j - 50 s_i)        -> sim_all = 0.5*T_all + 256.5
//   T_pos(i) = sum_j tanh(...) * t_j              -> sim_pos = 0.5*(T_pos - tanh(50 s_q - 50 s_i) + npos) + 0.5
//   ap[q] = (1/npos) * sum_{i: t=1} sim_pos/sim_all;  out = 1 - mean_q ap
//
// 512 blocks x 256 threads, zero smem, zero barriers, split-lane SHFL duo
// reduction (best measured). NEW vs R12: own-chunk data derived from the row
// cache registers (4 ballots + shfl broadcast) -- two fewer LDGs per warp.

static constexpr int BB = 512;
static constexpr unsigned long long NWARPS_TOTAL = 512ull * 8ull;   // 4096

// [63:13] fixed-point ap-sum (scale 2^32), [12:0] arrival count (max 4096).
__device__ unsigned long long g_accum = 0ull;

__device__ __forceinline__ float tanh_approx(float x) {
    float y;
    asm("tanh.approx.f32 %0, %1;" : "=f"(y) : "f"(x));
    return y;
}

__global__ __launch_bounds__(256) void smoothap_fused_kernel(
    const float* __restrict__ scores,
    const float* __restrict__ target,
    float* __restrict__ out)
{
    const int tid  = threadIdx.x;
    const int wid  = tid >> 5;        // 0..7
    const int lane = tid & 31;
    const int q    = blockIdx.x;

    const float* __restrict__ srow = scores + (size_t)q * BB;
    const float* __restrict__ trow = target + (size_t)q * BB;

    // full-row register cache (UNSCALED): 4 x LDG.128 each
    const float4* __restrict__ srow4 = reinterpret_cast<const float4*>(srow);
    const float4* __restrict__ trow4 = reinterpret_cast<const float4*>(trow);
    float4 sv[4], tv[4];
    #pragma unroll
    for (int k = 0; k < 4; ++k) {
        sv[k] = __ldg(srow4 + k * 32 + lane);
        tv[k] = __ldg(trow4 + k * 32 + lane);
    }
    const float sq = __ldg(srow + q);             // broadcast load, unscaled

    // ---- own-chunk mask from row cache: warp w owns cols [64w, 64w+64) ----
    // Those cols live in sv[k0]/tv[k0] of lanes [16*half, 16*half+16).
    const int k0   = wid >> 1;
    const int hsh  = (wid & 1) << 4;              // 0 or 16
    float4 svk, tvk;
    switch (k0) {   // compile-time-unrolled register select (k0 warp-constant)
        case 0: svk = sv[0]; tvk = tv[0]; break;
        case 1: svk = sv[1]; tvk = tv[1]; break;
        case 2: svk = sv[2]; tvk = tv[2]; break;
        default: svk = sv[3]; tvk = tv[3]; break;
    }
    const unsigned bx = __ballot_sync(0xffffffffu, tvk.x > 0.5f);
    const unsigned by = __ballot_sync(0xffffffffu, tvk.y > 0.5f);
    const unsigned bz = __ballot_sync(0xffffffffu, tvk.z > 0.5f);
    const unsigned bw = __ballot_sync(0xffffffffu, tvk.w > 0.5f);
    // j-grouped 64-bit mask: bit (16*j + i) -> col 128*k0 + 64*half + 4*i + j
    unsigned long long mm =
          (unsigned long long)((bx >> hsh) & 0xFFFFu)
        | ((unsigned long long)((by >> hsh) & 0xFFFFu) << 16)
        | ((unsigned long long)((bz >> hsh) & 0xFFFFu) << 32)
        | ((unsigned long long)((bw >> hsh) & 0xFFFFu) << 48);

    const bool hi_half = (lane >= 16);
    float acc = 0.0f;                 // lanes 0-15: A-terms, lanes 16-31: B-terms
    float fnp = 1.0f;

    if (mm) {
        // npos = sum(target row): lane partial + one xor reduce
        float ts = ((tv[0].x + tv[0].y) + (tv[0].z + tv[0].w))
                 + ((tv[1].x + tv[1].y) + (tv[1].z + tv[1].w))
                 + ((tv[2].x + tv[2].y) + (tv[2].z + tv[2].w))
                 + ((tv[3].x + tv[3].y) + (tv[3].z + tv[3].w));
        #pragma unroll
        for (int o = 16; o; o >>= 1) ts += __shfl_xor_sync(0xffffffffu, ts, o);
        fnp = ts;                     // exact small integer, >= 1

        do {
            const int b0 = __ffsll(mm) - 1;  mm &= mm - 1;
            const bool two = (mm != 0ull);
            int b1 = b0;
            if (two) { b1 = __ffsll(mm) - 1; mm &= mm - 1; }

            // -50*s_i from row-cache registers: component-select + shfl
            const int j0 = b0 >> 4, l0 = hsh + (b0 & 15);
            float e01 = (j0 & 1) ? svk.y : svk.x;
            float e23 = (j0 & 1) ? svk.w : svk.z;
            float ec0 = (j0 & 2) ? e23 : e01;
            const float nhiA = __shfl_sync(0xffffffffu, ec0, l0) * -50.0f;

            const int j1 = b1 >> 4, l1 = hsh + (b1 & 15);
            float f01 = (j1 & 1) ? svk.y : svk.x;
            float f23 = (j1 & 1) ? svk.w : svk.z;
            float fc1 = (j1 & 2) ? f23 : f01;
            const float nhiB = __shfl_sync(0xffffffffu, fc1, l1) * -50.0f;

            float aA = 0.0f, pA = 0.0f, aB = 0.0f, pB = 0.0f;
            #pragma unroll
            for (int k = 0; k < 4; ++k) {
                #define SRA_STEP(S, T)                                        \
                    { const float thA = tanh_approx(fmaf((S), 50.0f, nhiA));  \
                      const float thB = tanh_approx(fmaf((S), 50.0f, nhiB));  \
                      aA += thA; pA = fmaf(thA, (T), pA);                     \
                      aB += thB; pB = fmaf(thB, (T), pB); }
                SRA_STEP(sv[k].x, tv[k].x)
                SRA_STEP(sv[k].y, tv[k].y)
                SRA_STEP(sv[k].z, tv[k].z)
                SRA_STEP(sv[k].w, tv[k].w)
                #undef SRA_STEP
            }

            // split-lane reduction: one xor-16 level on all 4 accumulators,
            // then A -> lanes 0-15, B -> lanes 16-31, 4 more levels.
            aA += __shfl_xor_sync(0xffffffffu, aA, 16);
            pA += __shfl_xor_sync(0xffffffffu, pA, 16);
            aB += __shfl_xor_sync(0xffffffffu, aB, 16);
            pB += __shfl_xor_sync(0xffffffffu, pB, 16);
            float xa = hi_half ? aB : aA;
            float xp = hi_half ? pB : pA;
            #pragma unroll
            for (int o = 8; o; o >>= 1) {
                xa += __shfl_xor_sync(0xffffffffu, xa, o);
                xp += __shfl_xor_sync(0xffffffffu, xp, o);
            }

            // epilogue once: A-lanes and B-lanes in parallel
            const float nhi = hi_half ? nhiB : nhiA;
            const float thq = tanh_approx(fmaf(sq, 50.0f, nhi));
            float term = __fdividef(0.5f * (xp - thq + fnp) + 0.5f,
                                    0.5f * xa + 256.5f);
            if (!two && hi_half) term = 0.0f;   // single-pair duo: B is a dup
            acc += term;
        } while (mm);
    }

    // fold the two half-accumulators (fixed order -> deterministic)
    acc += __shfl_xor_sync(0xffffffffu, acc, 16);

    // ---- per-warp autonomous finish: one packed atomic, no barrier ----
    if (lane == 0) {
        const float w_ap = __fdividef(acc, fnp);   // this warp's share of ap[q]
        unsigned long long contrib =
            ((unsigned long long)__float2ull_rn(w_ap * 4294967296.0f) << 13) | 1ull;
        unsigned long long nv = atomicAdd(&g_accum, contrib) + contrib;

        if ((nv & 0x1FFFull) == NWARPS_TOTAL) {    // unique last-arriving warp
            const double sum_ap = (double)(nv >> 13) * (1.0 / 4294967296.0);
            out[0] = (float)(1.0 - sum_ap * (1.0 / (double)BB));
            atomicExch(&g_accum, 0ull);            // reset for next graph replay
        }
    }
}

extern "C" void kernel_launch(void* const* d_in, const int* in_sizes, int n_in,
                              void* d_out, int out_size)
{
    const float* scores = (const float*)d_in[0];
    const float* target = (const float*)d_in[1];
    smoothap_fused_kernel<<<BB, 256>>>(scores, target, (float*)d_out);
}